// round 1
// baseline (speedup 1.0000x reference)
#include <cuda_runtime.h>

#define Nn 100000
#define Ee 1600000
#define Dd 128
#define Ll 3
#define Gg 5000

// ---------------- scratch (device globals; no allocations allowed) ----------
__device__ float g_x[Nn * Dd];     // ping
__device__ float g_y[Nn * Dd];     // pong
__device__ float g_agg[Nn * Dd];   // mean-aggregated neighbors
__device__ float g_WT[7 * Dd * Dd];// k-major transposed weights: [Wl0,Wr0,Wl1,Wr1,Wl2,Wr2,W1]
__device__ int   g_deg[Nn];
__device__ float g_invdeg[Nn];
__device__ int   g_rowoff[Nn + 1];
__device__ int   g_cursor[Nn];
__device__ int   g_csr[Ee];        // src node per dst-sorted edge
__device__ int   g_part[256];
__device__ int   g_centers[Gg];

#define SCAN_B 256
#define SCAN_T 512
#define CHUNK ((Nn + SCAN_B - 1) / SCAN_B)   // 391

// ---------------- preprocessing kernels ------------------------------------
__global__ void k_zero_deg() {
    int i = blockIdx.x * blockDim.x + threadIdx.x;
    if (i < Nn) g_deg[i] = 0;
}

__global__ void k_deg(const int* __restrict__ dst) {
    int e = blockIdx.x * blockDim.x + threadIdx.x;
    if (e < Ee) atomicAdd(&g_deg[dst[e]], 1);
}

__global__ void k_scan1() {
    __shared__ int sh[SCAN_T];
    int b = blockIdx.x, t = threadIdx.x;
    int i = b * CHUNK + t;
    int v = (t < CHUNK && i < Nn) ? g_deg[i] : 0;
    sh[t] = v;
    __syncthreads();
    for (int off = 1; off < SCAN_T; off <<= 1) {
        int y = (t >= off) ? sh[t - off] : 0;
        __syncthreads();
        sh[t] += y;
        __syncthreads();
    }
    if (t < CHUNK && i < Nn) g_rowoff[i] = sh[t] - v;  // exclusive within chunk
    if (t == SCAN_T - 1) g_part[b] = sh[SCAN_T - 1];   // chunk total
}

__global__ void k_scan2() {
    __shared__ int sh[SCAN_B];
    int t = threadIdx.x;
    int v = g_part[t];
    sh[t] = v;
    __syncthreads();
    for (int off = 1; off < SCAN_B; off <<= 1) {
        int y = (t >= off) ? sh[t - off] : 0;
        __syncthreads();
        sh[t] += y;
        __syncthreads();
    }
    g_part[t] = sh[t] - v;  // exclusive scan of chunk totals
}

__global__ void k_scan3() {
    int b = blockIdx.x, t = threadIdx.x;
    int i = b * CHUNK + t;
    if (t < CHUNK && i < Nn) {
        int v = g_rowoff[i] + g_part[b];
        g_rowoff[i] = v;
        g_cursor[i] = v;
        int d = g_deg[i];
        g_invdeg[i] = 1.0f / (float)(d > 0 ? d : 1);
    }
    if (b == 0 && t == 0) g_rowoff[Nn] = Ee;
}

__global__ void k_csr(const int* __restrict__ src, const int* __restrict__ dst) {
    int e = blockIdx.x * blockDim.x + threadIdx.x;
    if (e < Ee) {
        int d = dst[e];
        int pos = atomicAdd(&g_cursor[d], 1);
        g_csr[pos] = src[e];
    }
}

__global__ void k_embed(const int* __restrict__ z, const float* __restrict__ zt) {
    int i = blockIdx.x * blockDim.x + threadIdx.x;   // Nn*32 float4 slots
    if (i >= Nn * 32) return;
    int n = i >> 5, q = i & 31;
    int zz = z[n];
    *(float4*)(g_x + n * Dd + q * 4) = *(const float4*)(zt + zz * Dd + q * 4);
}

// transpose all 7 weight matrices into k-major g_WT
__global__ void k_transpose(const float* __restrict__ Wl, const float* __restrict__ Wr,
                            const float* __restrict__ W1) {
    for (int i = blockIdx.x * blockDim.x + threadIdx.x; i < 7 * Dd * Dd;
         i += gridDim.x * blockDim.x) {
        int m = i >> 14;          // matrix id
        int k = (i >> 7) & 127;   // row in transposed = k
        int j = i & 127;          // col in transposed = output col
        const float* src;
        if (m < 6) {
            int l = m >> 1;
            src = (m & 1) ? (Wr + l * Dd * Dd) : (Wl + l * Dd * Dd);
        } else {
            src = W1;
        }
        g_WT[i] = src[j * Dd + k];
    }
}

__global__ void k_centers(const int* __restrict__ batch) {
    int g = blockIdx.x * blockDim.x + threadIdx.x;
    if (g >= Gg) return;
    int lo = 0, hi = Nn;
    while (lo < hi) {
        int mid = (lo + hi) >> 1;
        if (batch[mid] < g) lo = mid + 1; else hi = mid;
    }
    g_centers[g] = lo;
}

// ---------------- aggregation: warp-per-node CSR gather --------------------
__global__ void __launch_bounds__(256) k_agg(int xsel) {
    const float* __restrict__ x = xsel ? g_y : g_x;
    int w = (blockIdx.x * blockDim.x + threadIdx.x) >> 5;
    if (w >= Nn) return;
    int lane = threadIdx.x & 31;
    int beg = g_rowoff[w], end = g_rowoff[w + 1];
    float4 a0 = make_float4(0.f, 0.f, 0.f, 0.f);
    float4 a1 = make_float4(0.f, 0.f, 0.f, 0.f);
    int e = beg;
    for (; e + 2 <= end; e += 2) {
        int s0 = g_csr[e], s1 = g_csr[e + 1];
        float4 v0 = *(const float4*)(x + s0 * Dd + lane * 4);
        float4 v1 = *(const float4*)(x + s1 * Dd + lane * 4);
        a0.x += v0.x; a0.y += v0.y; a0.z += v0.z; a0.w += v0.w;
        a1.x += v1.x; a1.y += v1.y; a1.z += v1.z; a1.w += v1.w;
    }
    if (e < end) {
        int s0 = g_csr[e];
        float4 v0 = *(const float4*)(x + s0 * Dd + lane * 4);
        a0.x += v0.x; a0.y += v0.y; a0.z += v0.z; a0.w += v0.w;
    }
    float sc = g_invdeg[w];
    float4 r;
    r.x = (a0.x + a1.x) * sc; r.y = (a0.y + a1.y) * sc;
    r.z = (a0.z + a1.z) * sc; r.w = (a0.w + a1.w) * sc;
    *(float4*)(g_agg + w * Dd + lane * 4) = r;
}

// ---------------- layer GEMM: out = agg@WlT + x@WrT + b (relu optional) ----
// 128x128 tile per block, 256 threads, 8x8 micro-tiles.
#define GEMM_SMEM_FLOATS (128 * 128 + 128 * 36)
extern __shared__ float s_gemm[];

__global__ void __launch_bounds__(256, 2) k_gemm(int xsel, int layer,
                                                 const float* __restrict__ bias,
                                                 int relu) {
    float* sW = s_gemm;              // [128][128] k-major weight
    float* sA = s_gemm + 128 * 128;  // [128][36] input tile (row-major, padded)
    const float* __restrict__ X = xsel ? g_y : g_x;
    float* __restrict__ O = xsel ? g_x : g_y;

    int tid = threadIdx.x;
    int tx = tid & 15, ty = tid >> 4;
    int rowBase = blockIdx.x * 128;

    float acc[8][8];
#pragma unroll
    for (int r = 0; r < 8; r++)
#pragma unroll
        for (int c = 0; c < 8; c++) acc[r][c] = 0.f;

    for (int p = 0; p < 2; p++) {
        const float* __restrict__ W = g_WT + (2 * layer + p) * (Dd * Dd);
        const float* __restrict__ S = p ? X : g_agg;
        __syncthreads();  // prior pass done before overwriting sW/sA
#pragma unroll
        for (int i = tid; i < 4096; i += 256)
            ((float4*)sW)[i] = ((const float4*)W)[i];
        for (int kk = 0; kk < 4; kk++) {
            if (kk) __syncthreads();
#pragma unroll
            for (int i = tid; i < 1024; i += 256) {
                int r = i >> 3, q = i & 7;
                int row = rowBase + r;
                float4 v = make_float4(0.f, 0.f, 0.f, 0.f);
                if (row < Nn)
                    v = *(const float4*)(S + row * Dd + kk * 32 + q * 4);
                *(float4*)(sA + r * 36 + q * 4) = v;
            }
            __syncthreads();
#pragma unroll 4
            for (int k = 0; k < 32; k++) {
                const float* wr = sW + (kk * 32 + k) * 128 + tx * 8;
                float4 w0 = *(const float4*)wr;
                float4 w1 = *(const float4*)(wr + 4);
#pragma unroll
                for (int r = 0; r < 8; r++) {
                    float a = sA[(ty * 8 + r) * 36 + k];
                    acc[r][0] += a * w0.x; acc[r][1] += a * w0.y;
                    acc[r][2] += a * w0.z; acc[r][3] += a * w0.w;
                    acc[r][4] += a * w1.x; acc[r][5] += a * w1.y;
                    acc[r][6] += a * w1.z; acc[r][7] += a * w1.w;
                }
            }
        }
    }

    float bb[8];
#pragma unroll
    for (int c = 0; c < 8; c++) bb[c] = bias[tx * 8 + c];
#pragma unroll
    for (int r = 0; r < 8; r++) {
        int row = rowBase + ty * 8 + r;
        if (row < Nn) {
            float4 o0, o1;
            o0.x = acc[r][0] + bb[0]; o0.y = acc[r][1] + bb[1];
            o0.z = acc[r][2] + bb[2]; o0.w = acc[r][3] + bb[3];
            o1.x = acc[r][4] + bb[4]; o1.y = acc[r][5] + bb[5];
            o1.z = acc[r][6] + bb[6]; o1.w = acc[r][7] + bb[7];
            if (relu) {
                o0.x = fmaxf(o0.x, 0.f); o0.y = fmaxf(o0.y, 0.f);
                o0.z = fmaxf(o0.z, 0.f); o0.w = fmaxf(o0.w, 0.f);
                o1.x = fmaxf(o1.x, 0.f); o1.y = fmaxf(o1.y, 0.f);
                o1.z = fmaxf(o1.z, 0.f); o1.w = fmaxf(o1.w, 0.f);
            }
            *(float4*)(O + row * Dd + tx * 8) = o0;
            *(float4*)(O + row * Dd + tx * 8 + 4) = o1;
        }
    }
}

// ---------------- readout: h = x[c]*x[c+1]; relu(h@W1T+b1) @ W2T + b2 ------
__global__ void __launch_bounds__(128) k_readout(const float* __restrict__ b1,
                                                 const float* __restrict__ W2,
                                                 const float* __restrict__ b2,
                                                 float* __restrict__ out) {
    __shared__ float h[128];
    __shared__ float red[4];
    int g = blockIdx.x, j = threadIdx.x;
    int c = g_centers[g];
    h[j] = g_y[c * Dd + j] * g_y[(c + 1) * Dd + j];
    __syncthreads();
    float t = b1[j];
    const float* __restrict__ w1t = g_WT + 6 * Dd * Dd + j;
#pragma unroll 8
    for (int k = 0; k < 128; k++) t += h[k] * w1t[k * 128];
    t = fmaxf(t, 0.f) * W2[j];
    for (int off = 16; off; off >>= 1) t += __shfl_down_sync(0xffffffffu, t, off);
    if ((j & 31) == 0) red[j >> 5] = t;
    __syncthreads();
    if (j == 0) out[g] = red[0] + red[1] + red[2] + red[3] + b2[0];
}

// ---------------- launch ----------------------------------------------------
extern "C" void kernel_launch(void* const* d_in, const int* in_sizes, int n_in,
                              void* d_out, int out_size) {
    const int*   z     = (const int*)d_in[0];
    const int*   ei    = (const int*)d_in[1];
    const int*   batch = (const int*)d_in[2];
    const float* zt    = (const float*)d_in[3];
    const float* Wl    = (const float*)d_in[4];
    const float* bl    = (const float*)d_in[5];
    const float* Wr    = (const float*)d_in[6];
    const float* W1    = (const float*)d_in[7];
    const float* b1    = (const float*)d_in[8];
    const float* W2    = (const float*)d_in[9];
    const float* b2    = (const float*)d_in[10];
    float* out = (float*)d_out;

    const int* esrc = ei;
    const int* edst = ei + Ee;

    cudaFuncSetAttribute(k_gemm, cudaFuncAttributeMaxDynamicSharedMemorySize,
                         GEMM_SMEM_FLOATS * (int)sizeof(float));

    // CSR build + degrees
    k_zero_deg<<<(Nn + 255) / 256, 256>>>();
    k_deg<<<(Ee + 255) / 256, 256>>>(edst);
    k_scan1<<<SCAN_B, SCAN_T>>>();
    k_scan2<<<1, SCAN_B>>>();
    k_scan3<<<SCAN_B, SCAN_T>>>();
    k_csr<<<(Ee + 255) / 256, 256>>>(esrc, edst);

    // embedding, weight transposes, centers
    k_embed<<<(Nn * 32 + 255) / 256, 256>>>(z, zt);
    k_transpose<<<224, 256>>>(Wl, Wr, W1);
    k_centers<<<(Gg + 255) / 256, 256>>>(batch);

    // 3 SAGE layers (ping-pong g_x <-> g_y)
    int gemmGrid = (Nn + 127) / 128;  // 782
    int aggGrid  = (Nn * 32 + 255) / 256;
    for (int l = 0; l < Ll; l++) {
        int xsel = l & 1;  // x lives in g_x when xsel==0, g_y when xsel==1
        k_agg<<<aggGrid, 256>>>(xsel);
        k_gemm<<<gemmGrid, 256, GEMM_SMEM_FLOATS * (int)sizeof(float)>>>(
            xsel, l, bl + l * Dd, (l < Ll - 1) ? 1 : 0);
    }

    // readout (final x is in g_y after layer 2)
    k_readout<<<Gg, 128>>>(b1, W2, b2, out);
}